// round 10
// baseline (speedup 1.0000x reference)
#include <cuda_runtime.h>
#include <cstdint>

// Fixed problem shape: B=4, H=W=256, DIM=192, NH=6, HD=32, WS=8
// Pre-permuted / tf32-rounded weights
__device__ float g_wqh[110592];   // [6][96][192]  rows = [q(32)|k(32)|v(32)] of head h
__device__ float g_bqh[576];      // [6][96]
__device__ float g_woh[36864];    // [6][192][32]  woh[h][n][k] = out_w[n][h*32+k]

// ======================= helpers =======================
__device__ __forceinline__ uint32_t smem_u32(const void* p) {
    uint32_t a;
    asm("{ .reg .u64 t; cvta.to.shared.u64 t, %1; cvt.u32.u64 %0, t; }" : "=r"(a) : "l"(p));
    return a;
}
__device__ __forceinline__ void cp_async16(uint32_t dst, const void* src) {
    asm volatile("cp.async.cg.shared.global [%0], [%1], 16;" :: "r"(dst), "l"(src));
}
#define CP_COMMIT() asm volatile("cp.async.commit_group;" ::: "memory")
#define CP_WAIT0()  asm volatile("cp.async.wait_group 0;" ::: "memory")

__device__ __forceinline__ uint32_t to_tf32(float f) {
    uint32_t r;
    asm("cvt.rna.tf32.f32 %0, %1;" : "=r"(r) : "f"(f));
    return r;
}
__device__ __forceinline__ float rnd(float f) { return __uint_as_float(to_tf32(f)); }

__device__ __forceinline__ void mma_tf32(float* c, const uint32_t* a, uint32_t b0, uint32_t b1) {
    asm volatile(
        "mma.sync.aligned.m16n8k8.row.col.f32.tf32.tf32.f32 "
        "{%0,%1,%2,%3}, {%4,%5,%6,%7}, {%8,%9}, {%0,%1,%2,%3};"
        : "+f"(c[0]), "+f"(c[1]), "+f"(c[2]), "+f"(c[3])
        : "r"(a[0]), "r"(a[1]), "r"(a[2]), "r"(a[3]), "r"(b0), "r"(b1));
}

// ======================= weight pre-permute + tf32 round =======================
__global__ void wconv_kernel(const float* __restrict__ qkv_w, const float* __restrict__ qkv_b,
                             const float* __restrict__ out_w,
                             float* __restrict__ wqh, float* __restrict__ bqh,
                             float* __restrict__ woh) {
    int i0 = blockIdx.x * blockDim.x + threadIdx.x;
    int stride = gridDim.x * blockDim.x;
    for (int idx = i0; idx < 110592; idx += stride) {
        int h = idx / (96 * 192), rem = idx % (96 * 192);
        int j = rem / 192, k = rem % 192;
        int src = (j < 32) ? (h * 32 + j) : (j < 64) ? (192 + h * 32 + j - 32) : (384 + h * 32 + j - 64);
        wqh[idx] = rnd(qkv_w[src * 192 + k]);
    }
    for (int idx = i0; idx < 576; idx += stride) {
        int h = idx / 96, j = idx % 96;
        int src = (j < 32) ? (h * 32 + j) : (j < 64) ? (192 + h * 32 + j - 32) : (384 + h * 32 + j - 64);
        bqh[idx] = qkv_b[src];
    }
    for (int idx = i0; idx < 36864; idx += stride) {
        int h = idx / (192 * 32), rem = idx % (192 * 32);
        int n = rem / 32, k = rem % 32;
        woh[idx] = rnd(out_w[n * 192 + h * 32 + k]);
    }
}

// ======================= fully fused window kernel =======================
// one CTA = one window (64 tokens). 512 threads = 16 warps (4m x 4n).
// Weights stream from L2 as direct-LDG B-fragments (no smem staging).
// smem floats: sX 64x196 | sQK 64x68 (q|k) | sVt 32x68 | sP 64x68 | sO 64x36 | sPE 32x12 | sPEb 32
static const int FUSED_SMEM = (12544 + 4352 + 2176 + 4352 + 2304 + 384 + 32) * 4;  // 104,576 B

__global__ __launch_bounds__(512, 1) void fused_kernel(
    const float* __restrict__ x,
    const float* __restrict__ wqh, const float* __restrict__ bqh,
    const float* __restrict__ woh,
    const float* __restrict__ pe_w, const float* __restrict__ pe_b,
    const float* __restrict__ out_b, float* __restrict__ out)
{
    extern __shared__ float sm[];
    float* sX  = sm;            // 12544
    float* sQK = sX + 12544;    // 4352
    float* sVt = sQK + 4352;    // 2176
    float* sP  = sVt + 2176;    // 4352
    float* sO  = sP + 4352;     // 2304
    float* sPE = sO + 2304;     // 384
    float* sPEb = sPE + 384;    // 32

    const uint32_t uX = smem_u32(sX);

    const int tid = threadIdx.x;
    const int wid = tid >> 5, lane = tid & 31;
    const int wm = wid & 3, wn = wid >> 2;
    const int g = lane >> 2, tg = lane & 3;

    const int w = blockIdx.x;
    const int bb = w >> 10;
    const int wy = (w & 1023) >> 5, wx = w & 31;

    const int r0 = wm * 16 + g;   // m row (0..63); +8 for second half of m16 tile

    // ---- load X tile once (64 x 192, stride 196) ----
#pragma unroll
    for (int i = 0; i < 6; i++) {
        int idx = tid + i * 512;           // 3072 float4
        int t = idx / 48, c4 = idx % 48;
        int n = (wy * 8 + (t >> 3)) * 256 + wx * 8 + (t & 7);
        cp_async16(uX + (t * 196 + c4 * 4) * 4,
                   &x[((size_t)(bb * 65536 + n)) * 192 + c4 * 4]);
    }
    CP_COMMIT();

    float outacc[6][4];
#pragma unroll
    for (int i = 0; i < 6; i++)
#pragma unroll
        for (int j = 0; j < 4; j++) outacc[i][j] = 0.f;

    CP_WAIT0();
    __syncthreads();

#pragma unroll 1
    for (int h = 0; h < 6; h++) {
        // pe weights for this head (safe: all warps past previous head's D via sync)
        if (tid < 288) sPE[(tid / 9) * 12 + tid % 9] = pe_w[(h * 32 + tid / 9) * 9 + tid % 9];
        if (tid >= 480) sPEb[tid - 480] = pe_b[h * 32 + tid - 480];

        // ---- Phase A: QKV head-gemm  C(64x96) = X(64x192) @ Wh(96x192)^T ----
        // A-frags from sX (cvt), B-frags direct LDG from L2 (pre-rounded tf32).
        float acc[3][4];
#pragma unroll
        for (int i = 0; i < 3; i++)
#pragma unroll
            for (int j = 0; j < 4; j++) acc[i][j] = 0.f;

        const float* WhA = wqh + (size_t)h * 96 * 192;
#pragma unroll
        for (int kc = 0; kc < 6; kc++) {
#pragma unroll
            for (int ks = 0; ks < 4; ks++) {
                const int k0 = kc * 32 + ks * 8;
                uint32_t a[4];
                a[0] = to_tf32(sX[r0 * 196 + k0 + tg]);
                a[1] = to_tf32(sX[(r0 + 8) * 196 + k0 + tg]);
                a[2] = to_tf32(sX[r0 * 196 + k0 + tg + 4]);
                a[3] = to_tf32(sX[(r0 + 8) * 196 + k0 + tg + 4]);
#pragma unroll
                for (int nt = 0; nt < 3; nt++) {
                    int n0 = wn * 24 + nt * 8 + g;
                    uint32_t b0 = __float_as_uint(__ldg(&WhA[n0 * 192 + k0 + tg]));
                    uint32_t b1 = __float_as_uint(__ldg(&WhA[n0 * 192 + k0 + tg + 4]));
                    mma_tf32(acc[nt], a, b0, b1);
                }
            }
        }

        // Phase A epilogue: +bias, fold scale into q, round to tf32, scatter.
        const float scale = 0.17677669529663687f;
#pragma unroll
        for (int nt = 0; nt < 3; nt++) {
            int c = wn * 24 + nt * 8 + tg * 2;
            float b0v = __ldg(&bqh[h * 96 + c]), b1v = __ldg(&bqh[h * 96 + c + 1]);
            float v00 = acc[nt][0] + b0v, v01 = acc[nt][1] + b1v;
            float v10 = acc[nt][2] + b0v, v11 = acc[nt][3] + b1v;
            if (c < 32) {            // q (scale folded)
                sQK[r0 * 68 + c] = rnd(v00 * scale);       sQK[r0 * 68 + c + 1] = rnd(v01 * scale);
                sQK[(r0 + 8) * 68 + c] = rnd(v10 * scale); sQK[(r0 + 8) * 68 + c + 1] = rnd(v11 * scale);
            } else if (c < 64) {     // k
                sQK[r0 * 68 + c] = rnd(v00);       sQK[r0 * 68 + c + 1] = rnd(v01);
                sQK[(r0 + 8) * 68 + c] = rnd(v10); sQK[(r0 + 8) * 68 + c + 1] = rnd(v11);
            } else {                 // v -> transposed
                int d = c - 64;
                sVt[d * 68 + r0] = rnd(v00);       sVt[(d + 1) * 68 + r0] = rnd(v01);
                sVt[d * 68 + r0 + 8] = rnd(v10);   sVt[(d + 1) * 68 + r0 + 8] = rnd(v11);
            }
        }
        __syncthreads();

        // ---- Phase B: logits(64x64) = q @ k^T  (operands pre-rounded, no cvt) ----
        {
            float bacc[2][4];
#pragma unroll
            for (int i = 0; i < 2; i++)
#pragma unroll
                for (int j = 0; j < 4; j++) bacc[i][j] = 0.f;
#pragma unroll
            for (int ks = 0; ks < 4; ks++) {
                const int k0 = ks * 8;
                uint32_t a[4];
                a[0] = __float_as_uint(sQK[r0 * 68 + k0 + tg]);
                a[1] = __float_as_uint(sQK[(r0 + 8) * 68 + k0 + tg]);
                a[2] = __float_as_uint(sQK[r0 * 68 + k0 + tg + 4]);
                a[3] = __float_as_uint(sQK[(r0 + 8) * 68 + k0 + tg + 4]);
#pragma unroll
                for (int nt = 0; nt < 2; nt++) {
                    int n0 = wn * 16 + nt * 8 + g;
                    uint32_t b0 = __float_as_uint(sQK[n0 * 68 + 32 + k0 + tg]);
                    uint32_t b1 = __float_as_uint(sQK[n0 * 68 + 32 + k0 + tg + 4]);
                    mma_tf32(bacc[nt], a, b0, b1);
                }
            }
#pragma unroll
            for (int nt = 0; nt < 2; nt++) {
                int s = wn * 16 + nt * 8 + tg * 2;
                sP[r0 * 68 + s] = bacc[nt][0];
                sP[r0 * 68 + s + 1] = bacc[nt][1];
                sP[(r0 + 8) * 68 + s] = bacc[nt][2];
                sP[(r0 + 8) * 68 + s + 1] = bacc[nt][3];
            }
        }
        __syncthreads();

        // ---- Phase C: softmax over s (8 lanes per row); write rounded tf32 ----
        {
            int t = tid >> 3, q = tid & 7;
            float* row = sP + t * 68 + q * 8;
            float4 x0 = *(float4*)row;
            float4 x1 = *(float4*)(row + 4);
            float m = fmaxf(fmaxf(fmaxf(x0.x, x0.y), fmaxf(x0.z, x0.w)),
                            fmaxf(fmaxf(x1.x, x1.y), fmaxf(x1.z, x1.w)));
            m = fmaxf(m, __shfl_xor_sync(0xffffffffu, m, 1));
            m = fmaxf(m, __shfl_xor_sync(0xffffffffu, m, 2));
            m = fmaxf(m, __shfl_xor_sync(0xffffffffu, m, 4));
            float e0 = __expf(x0.x - m), e1 = __expf(x0.y - m), e2 = __expf(x0.z - m), e3 = __expf(x0.w - m);
            float e4 = __expf(x1.x - m), e5 = __expf(x1.y - m), e6 = __expf(x1.z - m), e7 = __expf(x1.w - m);
            float s = e0 + e1 + e2 + e3 + e4 + e5 + e6 + e7;
            s += __shfl_xor_sync(0xffffffffu, s, 1);
            s += __shfl_xor_sync(0xffffffffu, s, 2);
            s += __shfl_xor_sync(0xffffffffu, s, 4);
            float inv = 1.0f / s;
            row[0] = rnd(e0 * inv); row[1] = rnd(e1 * inv); row[2] = rnd(e2 * inv); row[3] = rnd(e3 * inv);
            row[4] = rnd(e4 * inv); row[5] = rnd(e5 * inv); row[6] = rnd(e6 * inv); row[7] = rnd(e7 * inv);
        }
        __syncthreads();

        // ---- Phase D: o(64x32) = P @ v, + fused LePE; write rounded to sO ----
        {
            float dacc[4] = {0.f, 0.f, 0.f, 0.f};
            const int n0 = wn * 8 + g;
#pragma unroll
            for (int ks = 0; ks < 8; ks++) {
                const int k0 = ks * 8;
                uint32_t a[4];
                a[0] = __float_as_uint(sP[r0 * 68 + k0 + tg]);
                a[1] = __float_as_uint(sP[(r0 + 8) * 68 + k0 + tg]);
                a[2] = __float_as_uint(sP[r0 * 68 + k0 + tg + 4]);
                a[3] = __float_as_uint(sP[(r0 + 8) * 68 + k0 + tg + 4]);
                uint32_t b0 = __float_as_uint(sVt[n0 * 68 + k0 + tg]);
                uint32_t b1 = __float_as_uint(sVt[n0 * 68 + k0 + tg + 4]);
                mma_tf32(dacc, a, b0, b1);
            }
            // LePE: depthwise 3x3 per channel d over the 8x8 window
            const int d0 = wn * 8 + tg * 2;
            float w9a[9], w9b[9];
#pragma unroll
            for (int j = 0; j < 9; j++) { w9a[j] = sPE[d0 * 12 + j]; w9b[j] = sPE[(d0 + 1) * 12 + j]; }
            float pb0 = sPEb[d0], pb1 = sPEb[d0 + 1];
#pragma unroll
            for (int i = 0; i < 2; i++) {
                int t = r0 + i * 8;
                int ty = t >> 3, tx = t & 7;
                float l0 = pb0, l1 = pb1;
#pragma unroll
                for (int ky = 0; ky < 3; ky++) {
                    int yy = ty + ky - 1;
                    if (yy < 0 || yy > 7) continue;
#pragma unroll
                    for (int kx = 0; kx < 3; kx++) {
                        int xx = tx + kx - 1;
                        if (xx < 0 || xx > 7) continue;
                        int ss = yy * 8 + xx;
                        l0 += w9a[ky * 3 + kx] * sVt[d0 * 68 + ss];
                        l1 += w9b[ky * 3 + kx] * sVt[(d0 + 1) * 68 + ss];
                    }
                }
                sO[t * 36 + d0] = rnd(dacc[2 * i] + l0);
                sO[t * 36 + d0 + 1] = rnd(dacc[2 * i + 1] + l1);
            }
        }
        __syncthreads();

        // ---- Phase F: out(64x192) += o(64x32) @ woh[h](192x32)^T  (B via LDG) ----
        const float* WhO = woh + (size_t)h * 192 * 32;
#pragma unroll
        for (int ks = 0; ks < 4; ks++) {
            const int k0 = ks * 8;
            uint32_t a[4];
            a[0] = __float_as_uint(sO[r0 * 36 + k0 + tg]);
            a[1] = __float_as_uint(sO[(r0 + 8) * 36 + k0 + tg]);
            a[2] = __float_as_uint(sO[r0 * 36 + k0 + tg + 4]);
            a[3] = __float_as_uint(sO[(r0 + 8) * 36 + k0 + tg + 4]);
#pragma unroll
            for (int nt = 0; nt < 6; nt++) {
                int n0 = wn * 48 + nt * 8 + g;
                uint32_t b0 = __float_as_uint(__ldg(&WhO[n0 * 32 + k0 + tg]));
                uint32_t b1 = __float_as_uint(__ldg(&WhO[n0 * 32 + k0 + tg + 4]));
                mma_tf32(outacc[nt], a, b0, b1);
            }
        }
        // no end-of-head sync needed: next phase-A writes (sQK/sVt epilogue) are
        // gated by the post-epilogue sync, and F reads only sO + global.
    }

    // ---- final epilogue: + out_b, store to (B, N, C) ----
    const int t0 = r0, t1 = r0 + 8;
    const int n0g = (wy * 8 + (t0 >> 3)) * 256 + wx * 8 + (t0 & 7);
    const int n1g = (wy * 8 + (t1 >> 3)) * 256 + wx * 8 + (t1 & 7);
    const size_t base0 = ((size_t)(bb * 65536 + n0g)) * 192;
    const size_t base1 = ((size_t)(bb * 65536 + n1g)) * 192;
#pragma unroll
    for (int nt = 0; nt < 6; nt++) {
        int col = wn * 48 + nt * 8 + tg * 2;
        float2 ob = *(const float2*)&out_b[col];
        *(float2*)&out[base0 + col] = make_float2(outacc[nt][0] + ob.x, outacc[nt][1] + ob.y);
        *(float2*)&out[base1 + col] = make_float2(outacc[nt][2] + ob.x, outacc[nt][3] + ob.y);
    }
}

// ======================= launcher =======================
extern "C" void kernel_launch(void* const* d_in, const int* in_sizes, int n_in,
                              void* d_out, int out_size) {
    const float* x     = (const float*)d_in[0];
    const float* qkv_w = (const float*)d_in[1];
    const float* qkv_b = (const float*)d_in[2];
    const float* pe_w  = (const float*)d_in[3];
    const float* pe_b  = (const float*)d_in[4];
    const float* out_w = (const float*)d_in[5];
    const float* out_b = (const float*)d_in[6];
    float* out = (float*)d_out;

    const int B = in_sizes[0] / (65536 * 192);

    float *wqh_s, *bqh_s, *woh_s;
    cudaGetSymbolAddress((void**)&wqh_s, g_wqh);
    cudaGetSymbolAddress((void**)&bqh_s, g_bqh);
    cudaGetSymbolAddress((void**)&woh_s, g_woh);

    static bool attr_set = false;
    if (!attr_set) {
        cudaFuncSetAttribute(fused_kernel, cudaFuncAttributeMaxDynamicSharedMemorySize, FUSED_SMEM);
        attr_set = true;
    }

    wconv_kernel<<<144, 256>>>(qkv_w, qkv_b, out_w, wqh_s, bqh_s, woh_s);

    fused_kernel<<<B * 1024, 512, FUSED_SMEM>>>(
        x, wqh_s, bqh_s, woh_s, pe_w, pe_b, out_b, out);
}

// round 11
// speedup vs baseline: 2.3745x; 2.3745x over previous
#include <cuda_runtime.h>
#include <cstdint>

// Fixed problem shape: B=4, H=W=256, DIM=192, NH=6, HD=32, WS=8
__device__ float g_qkv[150994944];   // B*65536*576
__device__ float g_o[50331648];      // B*65536*192
__device__ float g_wq[110592];       // qkv_w pre-rounded to tf32
__device__ float g_wo[36864];        // out_w pre-rounded to tf32

// ======================= helpers =======================
__device__ __forceinline__ uint32_t smem_u32(const void* p) {
    uint32_t a;
    asm("{ .reg .u64 t; cvta.to.shared.u64 t, %1; cvt.u32.u64 %0, t; }" : "=r"(a) : "l"(p));
    return a;
}
__device__ __forceinline__ void cp_async16(uint32_t dst, const void* src) {
    asm volatile("cp.async.cg.shared.global [%0], [%1], 16;" :: "r"(dst), "l"(src));
}
#define CP_COMMIT() asm volatile("cp.async.commit_group;" ::: "memory")
#define CP_WAIT1()  asm volatile("cp.async.wait_group 1;" ::: "memory")
#define CP_WAIT0()  asm volatile("cp.async.wait_group 0;" ::: "memory")

__device__ __forceinline__ uint32_t to_tf32(float f) {
    uint32_t r;
    asm("cvt.rna.tf32.f32 %0, %1;" : "=r"(r) : "f"(f));
    return r;
}
__device__ __forceinline__ float rnd(float f) { return __uint_as_float(to_tf32(f)); }

__device__ __forceinline__ void mma_tf32(float* c, const uint32_t* a, uint32_t b0, uint32_t b1) {
    asm volatile(
        "mma.sync.aligned.m16n8k8.row.col.f32.tf32.tf32.f32 "
        "{%0,%1,%2,%3}, {%4,%5,%6,%7}, {%8,%9}, {%0,%1,%2,%3};"
        : "+f"(c[0]), "+f"(c[1]), "+f"(c[2]), "+f"(c[3])
        : "r"(a[0]), "r"(a[1]), "r"(a[2]), "r"(a[3]), "r"(b0), "r"(b1));
}

// ======================= weight pre-round =======================
__global__ void wconv_kernel(const float* __restrict__ w1, float* __restrict__ o1, int n1,
                             const float* __restrict__ w2, float* __restrict__ o2, int n2) {
    int i = blockIdx.x * blockDim.x + threadIdx.x;
    int stride = gridDim.x * blockDim.x;
    for (int j = i; j < n1; j += stride) o1[j] = rnd(w1[j]);
    for (int j = i; j < n2; j += stride) o2[j] = rnd(w2[j]);
}

// ======================= tf32 mma.sync GEMM (2 CTAs/SM) =======================
// C[M,N] = A[M,K] @ W[N,K]^T + bias.  W pre-rounded tf32.
// CTA tile 64(M) x 96(N), BK=32, 256 threads = 8 warps (4m x 2n), warp 16x48.
#define APAD 36
__global__ __launch_bounds__(256, 2) void gemm_tc(
    const float* __restrict__ A, const float* __restrict__ W,
    const float* __restrict__ bias, float* __restrict__ C,
    int M, int N, int K)
{
    __shared__ float sA[2][64 * APAD];
    __shared__ float sB[2][96 * APAD];
    const uint32_t aU[2] = { smem_u32(sA[0]), smem_u32(sA[1]) };
    const uint32_t bU[2] = { smem_u32(sB[0]), smem_u32(sB[1]) };

    const int tid = threadIdx.x;
    const int bm = blockIdx.y * 64;
    const int bn = blockIdx.x * 96;
    const int nch = K / 32;

    const int wid = tid >> 5, lane = tid & 31;
    const int wm = wid & 3;        // m: wm*16
    const int wn = wid >> 2;       // n: wn*48
    const int g = lane >> 2, tg = lane & 3;

    float acc[6][4];
#pragma unroll
    for (int nt = 0; nt < 6; nt++)
#pragma unroll
        for (int j = 0; j < 4; j++) acc[nt][j] = 0.f;

    auto load_tile = [&](int kc, int bsel) {
#pragma unroll
        for (int i = 0; i < 2; i++) {              // A: 512 float4
            int idx = tid + i * 256;
            int row = idx >> 3, c4 = idx & 7;
            cp_async16(aU[bsel] + (row * APAD + c4 * 4) * 4,
                       &A[(size_t)(bm + row) * K + kc * 32 + c4 * 4]);
        }
#pragma unroll
        for (int i = 0; i < 3; i++) {              // B: 768 float4
            int idx = tid + i * 256;
            int row = idx >> 3, c4 = idx & 7;
            cp_async16(bU[bsel] + (row * APAD + c4 * 4) * 4,
                       &W[(size_t)(bn + row) * K + kc * 32 + c4 * 4]);
        }
    };

    load_tile(0, 0); CP_COMMIT();
    load_tile(1, 1); CP_COMMIT();

    const int r0 = wm * 16 + g;
    for (int kc = 0; kc < nch; kc++) {
        const int bsel = kc & 1;
        CP_WAIT1();
        __syncthreads();

        const float* As = sA[bsel];
        const float* Bs = sB[bsel];
#pragma unroll
        for (int ks = 0; ks < 4; ks++) {
            const int k0 = ks * 8;
            uint32_t a[4];
            a[0] = to_tf32(As[r0 * APAD + k0 + tg]);
            a[1] = to_tf32(As[(r0 + 8) * APAD + k0 + tg]);
            a[2] = to_tf32(As[r0 * APAD + k0 + tg + 4]);
            a[3] = to_tf32(As[(r0 + 8) * APAD + k0 + tg + 4]);
#pragma unroll
            for (int nt = 0; nt < 6; nt++) {
                int n0 = wn * 48 + nt * 8 + g;
                uint32_t b0 = __float_as_uint(Bs[n0 * APAD + k0 + tg]);   // pre-tf32
                uint32_t b1 = __float_as_uint(Bs[n0 * APAD + k0 + tg + 4]);
                mma_tf32(acc[nt], a, b0, b1);
            }
        }
        __syncthreads();
        if (kc + 2 < nch) load_tile(kc + 2, bsel);
        CP_COMMIT();
    }

    // epilogue: bias + store
    const int row0 = bm + r0;
#pragma unroll
    for (int nt = 0; nt < 6; nt++) {
        int col = bn + wn * 48 + nt * 8 + tg * 2;
        float2 bb = *(const float2*)&bias[col];
        *(float2*)&C[(size_t)row0 * N + col] =
            make_float2(acc[nt][0] + bb.x, acc[nt][1] + bb.y);
        *(float2*)&C[(size_t)(row0 + 8) * N + col] =
            make_float2(acc[nt][2] + bb.x, acc[nt][3] + bb.y);
    }
}

// ======================= tensorized windowed attention + LePE =======================
// one CTA = one (window, head). 128 threads = 4 warps. grid (4096, 6).
__global__ __launch_bounds__(128) void attn_kernel(
    const float* __restrict__ qkv, const float* __restrict__ pe_w,
    const float* __restrict__ pe_b, float* __restrict__ O)
{
    __shared__ float sQ[64 * 36];    // raw q
    __shared__ float sK[64 * 36];    // raw k
    __shared__ float sVt[32 * 68];   // v transposed [d][s], tf32-rounded
    __shared__ float sP[64 * 68];    // logits -> probs; first 64*36 used as raw-v staging
    __shared__ float sPE[32 * 12];
    __shared__ float sPEb[32];

    const uint32_t uQ = smem_u32(sQ), uK = smem_u32(sK), uVr = smem_u32(sP);

    const int w = blockIdx.x;
    const int h = blockIdx.y;
    const int bb = w >> 10;
    const int wy = (w & 1023) >> 5, wx = w & 31;
    const int tid = threadIdx.x;
    const int wid = tid >> 5, lane = tid & 31;
    const int g = lane >> 2, tg = lane & 3;

    // ---- gather q,k,v via cp.async (16B each) ----
#pragma unroll
    for (int i = 0; i < 12; i++) {
        int idx = tid + i * 128;        // 1536 float4
        int t = idx / 24, j = idx % 24;
        int which = j >> 3, c4 = j & 7;
        int n = (wy * 8 + (t >> 3)) * 256 + wx * 8 + (t & 7);
        const float* src = &qkv[((size_t)(bb * 65536 + n)) * 576 + h * 32 + which * 192 + c4 * 4];
        uint32_t dst = (which == 0 ? uQ : which == 1 ? uK : uVr) + (t * 36 + c4 * 4) * 4;
        cp_async16(dst, src);
    }
    CP_COMMIT();
    // pe weights
    for (int i = tid; i < 288; i += 128)
        sPE[(i / 9) * 12 + i % 9] = pe_w[h * 288 + i];
    if (tid < 32) sPEb[tid] = pe_b[h * 32 + tid];
    CP_WAIT0();
    __syncthreads();

    // ---- transpose v (raw in sP region) -> sVt[d][s], rounded ----
#pragma unroll
    for (int i = 0; i < 16; i++) {
        int idx = tid + i * 128;
        int s = idx >> 5, d = idx & 31;
        sVt[d * 68 + s] = rnd(sP[s * 36 + d]);
    }
    __syncthreads();

    // ---- logits(64x64) = q @ k^T, scaled; warp wid owns m-tile rows wid*16.. ----
    const int r0 = wid * 16 + g;
    {
        float bacc[8][4];
#pragma unroll
        for (int nt = 0; nt < 8; nt++)
#pragma unroll
            for (int j = 0; j < 4; j++) bacc[nt][j] = 0.f;
#pragma unroll
        for (int ks = 0; ks < 4; ks++) {
            const int k0 = ks * 8;
            uint32_t a[4];
            a[0] = to_tf32(sQ[r0 * 36 + k0 + tg]);
            a[1] = to_tf32(sQ[(r0 + 8) * 36 + k0 + tg]);
            a[2] = to_tf32(sQ[r0 * 36 + k0 + tg + 4]);
            a[3] = to_tf32(sQ[(r0 + 8) * 36 + k0 + tg + 4]);
#pragma unroll
            for (int nt = 0; nt < 8; nt++) {
                int n0 = nt * 8 + g;
                uint32_t b0 = to_tf32(sK[n0 * 36 + k0 + tg]);
                uint32_t b1 = to_tf32(sK[n0 * 36 + k0 + tg + 4]);
                mma_tf32(bacc[nt], a, b0, b1);
            }
        }
        const float scale = 0.17677669529663687f;
#pragma unroll
        for (int nt = 0; nt < 8; nt++) {
            int s = nt * 8 + tg * 2;
            sP[r0 * 68 + s]       = bacc[nt][0] * scale;
            sP[r0 * 68 + s + 1]   = bacc[nt][1] * scale;
            sP[(r0 + 8) * 68 + s]     = bacc[nt][2] * scale;
            sP[(r0 + 8) * 68 + s + 1] = bacc[nt][3] * scale;
        }
    }
    __syncthreads();

    // ---- softmax: 2 threads per row, 32 cols each; write rounded probs ----
    {
        int t = tid >> 1, q = tid & 1;
        float* row = sP + t * 68 + q * 32;
        float v[32];
#pragma unroll
        for (int j = 0; j < 8; j++) *(float4*)&v[j * 4] = *(float4*)&row[j * 4];
        float m = v[0];
#pragma unroll
        for (int j = 1; j < 32; j++) m = fmaxf(m, v[j]);
        m = fmaxf(m, __shfl_xor_sync(0xffffffffu, m, 1));
        float s = 0.f;
#pragma unroll
        for (int j = 0; j < 32; j++) { v[j] = __expf(v[j] - m); s += v[j]; }
        s += __shfl_xor_sync(0xffffffffu, s, 1);
        float inv = 1.0f / s;
#pragma unroll
        for (int j = 0; j < 32; j++) v[j] = rnd(v[j] * inv);
#pragma unroll
        for (int j = 0; j < 8; j++) *(float4*)&row[j * 4] = *(float4*)&v[j * 4];
    }
    __syncthreads();

    // ---- PV: o(64x32) = P @ v  (operands pre-rounded), + LePE, store ----
    {
        float dacc[4][4];
#pragma unroll
        for (int nt = 0; nt < 4; nt++)
#pragma unroll
            for (int j = 0; j < 4; j++) dacc[nt][j] = 0.f;
#pragma unroll
        for (int ks = 0; ks < 8; ks++) {
            const int k0 = ks * 8;
            uint32_t a[4];
            a[0] = __float_as_uint(sP[r0 * 68 + k0 + tg]);
            a[1] = __float_as_uint(sP[(r0 + 8) * 68 + k0 + tg]);
            a[2] = __float_as_uint(sP[r0 * 68 + k0 + tg + 4]);
            a[3] = __float_as_uint(sP[(r0 + 8) * 68 + k0 + tg + 4]);
#pragma unroll
            for (int nt = 0; nt < 4; nt++) {
                int n0 = nt * 8 + g;
                uint32_t b0 = __float_as_uint(sVt[n0 * 68 + k0 + tg]);
                uint32_t b1 = __float_as_uint(sVt[n0 * 68 + k0 + tg + 4]);
                mma_tf32(dacc[nt], a, b0, b1);
            }
        }
        // LePE + store: thread owns (rows r0, r0+8) x (d0, d0+1) for each nt
#pragma unroll
        for (int nt = 0; nt < 4; nt++) {
            const int d0 = nt * 8 + tg * 2;
            float pb0 = sPEb[d0], pb1 = sPEb[d0 + 1];
#pragma unroll
            for (int i = 0; i < 2; i++) {
                int t = r0 + i * 8;
                int ty = t >> 3, tx = t & 7;
                float l0 = pb0, l1 = pb1;
#pragma unroll
                for (int ky = 0; ky < 3; ky++) {
                    int yy = ty + ky - 1;
                    if (yy < 0 || yy > 7) continue;
#pragma unroll
                    for (int kx = 0; kx < 3; kx++) {
                        int xx = tx + kx - 1;
                        if (xx < 0 || xx > 7) continue;
                        int ss = yy * 8 + xx;
                        l0 += sPE[d0 * 12 + ky * 3 + kx] * sVt[d0 * 68 + ss];
                        l1 += sPE[(d0 + 1) * 12 + ky * 3 + kx] * sVt[(d0 + 1) * 68 + ss];
                    }
                }
                int n = (wy * 8 + ty) * 256 + wx * 8 + tx;
                size_t base = ((size_t)(bb * 65536 + n)) * 192 + h * 32 + d0;
                *(float2*)&O[base] = make_float2(dacc[nt][2 * i] + l0, dacc[nt][2 * i + 1] + l1);
            }
        }
    }
}

// ======================= launcher =======================
extern "C" void kernel_launch(void* const* d_in, const int* in_sizes, int n_in,
                              void* d_out, int out_size) {
    const float* x     = (const float*)d_in[0];
    const float* qkv_w = (const float*)d_in[1];
    const float* qkv_b = (const float*)d_in[2];
    const float* pe_w  = (const float*)d_in[3];
    const float* pe_b  = (const float*)d_in[4];
    const float* out_w = (const float*)d_in[5];
    const float* out_b = (const float*)d_in[6];
    float* out = (float*)d_out;

    const int B = in_sizes[0] / (65536 * 192);
    const int M = B * 65536;

    float *qkv_s, *o_s, *wq_s, *wo_s;
    cudaGetSymbolAddress((void**)&qkv_s, g_qkv);
    cudaGetSymbolAddress((void**)&o_s, g_o);
    cudaGetSymbolAddress((void**)&wq_s, g_wq);
    cudaGetSymbolAddress((void**)&wo_s, g_wo);

    wconv_kernel<<<144, 256>>>(qkv_w, wq_s, 110592, out_w, wo_s, 36864);

    dim3 g1(6, M / 64);
    gemm_tc<<<g1, 256>>>(x, wq_s, qkv_b, qkv_s, M, 576, 192);

    dim3 g2(B * 1024, 6);
    attn_kernel<<<g2, 128>>>(qkv_s, pe_w, pe_b, o_s);

    dim3 g3(2, M / 64);
    gemm_tc<<<g3, 256>>>(o_s, wo_s, out_b, out, M, 192, 192);
}

// round 13
// speedup vs baseline: 2.5237x; 1.0629x over previous
#include <cuda_runtime.h>
#include <cstdint>

// Fixed problem shape: B=4, H=W=256, DIM=192, NH=6, HD=32, WS=8
__device__ float g_qkv[150994944];   // B*65536*576
__device__ float g_o[50331648];      // B*65536*192
__device__ float g_wq[110592];       // qkv_w pre-rounded to tf32
__device__ float g_wo[36864];        // out_w pre-rounded to tf32

// ======================= helpers =======================
__device__ __forceinline__ uint32_t smem_u32(const void* p) {
    uint32_t a;
    asm("{ .reg .u64 t; cvta.to.shared.u64 t, %1; cvt.u32.u64 %0, t; }" : "=r"(a) : "l"(p));
    return a;
}
__device__ __forceinline__ void cp_async16(uint32_t dst, const void* src) {
    asm volatile("cp.async.cg.shared.global [%0], [%1], 16;" :: "r"(dst), "l"(src));
}
#define CP_COMMIT() asm volatile("cp.async.commit_group;" ::: "memory")
#define CP_WAIT1()  asm volatile("cp.async.wait_group 1;" ::: "memory")
#define CP_WAIT0()  asm volatile("cp.async.wait_group 0;" ::: "memory")

__device__ __forceinline__ uint32_t to_tf32(float f) {
    uint32_t r;
    asm("cvt.rna.tf32.f32 %0, %1;" : "=r"(r) : "f"(f));
    return r;
}
__device__ __forceinline__ float rnd(float f) { return __uint_as_float(to_tf32(f)); }

__device__ __forceinline__ void mma_tf32(float* c, const uint32_t* a, uint32_t b0, uint32_t b1) {
    asm volatile(
        "mma.sync.aligned.m16n8k8.row.col.f32.tf32.tf32.f32 "
        "{%0,%1,%2,%3}, {%4,%5,%6,%7}, {%8,%9}, {%0,%1,%2,%3};"
        : "+f"(c[0]), "+f"(c[1]), "+f"(c[2]), "+f"(c[3])
        : "r"(a[0]), "r"(a[1]), "r"(a[2]), "r"(a[3]), "r"(b0), "r"(b1));
}

// ======================= weight pre-round =======================
__global__ void wconv_kernel(const float* __restrict__ w1, float* __restrict__ o1, int n1,
                             const float* __restrict__ w2, float* __restrict__ o2, int n2) {
    int i = blockIdx.x * blockDim.x + threadIdx.x;
    int stride = gridDim.x * blockDim.x;
    for (int j = i; j < n1; j += stride) o1[j] = rnd(w1[j]);
    for (int j = i; j < n2; j += stride) o2[j] = rnd(w2[j]);
}

// ======================= tf32 mma.sync GEMM (128x96 tile, 2 CTAs/SM) =======================
// C[M,N] = A[M,K] @ W[N,K]^T + bias.  W pre-rounded tf32.
// CTA tile 128(M) x 96(N), BK=32, 256 threads = 8 warps (4m x 2n), warp 32x48.
#define APAD 36
static const int GEMM_SMEM = 2 * (128 + 96) * APAD * 4;   // 64512 B dynamic

__global__ __launch_bounds__(256, 2) void gemm_tc(
    const float* __restrict__ A, const float* __restrict__ W,
    const float* __restrict__ bias, float* __restrict__ C,
    int M, int N, int K)
{
    extern __shared__ float smem[];
    float* sAp[2] = { smem,              smem + (128 + 96) * APAD };
    float* sBp[2] = { smem + 128 * APAD, smem + (128 + 96) * APAD + 128 * APAD };
    const uint32_t aU[2] = { smem_u32(sAp[0]), smem_u32(sAp[1]) };
    const uint32_t bU[2] = { smem_u32(sBp[0]), smem_u32(sBp[1]) };

    const int tid = threadIdx.x;
    const int bm = blockIdx.y * 128;
    const int bn = blockIdx.x * 96;
    const int nch = K / 32;

    const int wid = tid >> 5, lane = tid & 31;
    const int wm = wid & 3;        // m: wm*32 (two m16 tiles)
    const int wn = wid >> 2;       // n: wn*48 (six n8 tiles)
    const int g = lane >> 2, tg = lane & 3;

    float acc[2][6][4];
#pragma unroll
    for (int mt = 0; mt < 2; mt++)
#pragma unroll
        for (int nt = 0; nt < 6; nt++)
#pragma unroll
            for (int j = 0; j < 4; j++) acc[mt][nt][j] = 0.f;

    auto load_tile = [&](int kc, int bsel) {
#pragma unroll
        for (int i = 0; i < 4; i++) {              // A: 1024 float4
            int idx = tid + i * 256;
            int row = idx >> 3, c4 = idx & 7;
            cp_async16(aU[bsel] + (row * APAD + c4 * 4) * 4,
                       &A[(size_t)(bm + row) * K + kc * 32 + c4 * 4]);
        }
#pragma unroll
        for (int i = 0; i < 3; i++) {              // B: 768 float4
            int idx = tid + i * 256;
            int row = idx >> 3, c4 = idx & 7;
            cp_async16(bU[bsel] + (row * APAD + c4 * 4) * 4,
                       &W[(size_t)(bn + row) * K + kc * 32 + c4 * 4]);
        }
    };

    load_tile(0, 0); CP_COMMIT();
    load_tile(1, 1); CP_COMMIT();

    for (int kc = 0; kc < nch; kc++) {
        const int bsel = kc & 1;
        CP_WAIT1();
        __syncthreads();

        const float* As = sAp[bsel];
        const float* Bs = sBp[bsel];
#pragma unroll
        for (int ks = 0; ks < 4; ks++) {
            const int k0 = ks * 8;
            uint32_t a[2][4];
#pragma unroll
            for (int mt = 0; mt < 2; mt++) {
                int rr = wm * 32 + mt * 16 + g;
                a[mt][0] = to_tf32(As[rr * APAD + k0 + tg]);
                a[mt][1] = to_tf32(As[(rr + 8) * APAD + k0 + tg]);
                a[mt][2] = to_tf32(As[rr * APAD + k0 + tg + 4]);
                a[mt][3] = to_tf32(As[(rr + 8) * APAD + k0 + tg + 4]);
            }
#pragma unroll
            for (int nt = 0; nt < 6; nt++) {
                int n0 = wn * 48 + nt * 8 + g;
                uint32_t b0 = __float_as_uint(Bs[n0 * APAD + k0 + tg]);   // pre-tf32
                uint32_t b1 = __float_as_uint(Bs[n0 * APAD + k0 + tg + 4]);
                mma_tf32(acc[0][nt], a[0], b0, b1);
                mma_tf32(acc[1][nt], a[1], b0, b1);
            }
        }
        __syncthreads();
        if (kc + 2 < nch) load_tile(kc + 2, bsel);
        CP_COMMIT();
    }

    // epilogue: bias + store
#pragma unroll
    for (int mt = 0; mt < 2; mt++) {
        const int row0 = bm + wm * 32 + mt * 16 + g;
#pragma unroll
        for (int nt = 0; nt < 6; nt++) {
            int col = bn + wn * 48 + nt * 8 + tg * 2;
            float2 bb = *(const float2*)&bias[col];
            *(float2*)&C[(size_t)row0 * N + col] =
                make_float2(acc[mt][nt][0] + bb.x, acc[mt][nt][1] + bb.y);
            *(float2*)&C[(size_t)(row0 + 8) * N + col] =
                make_float2(acc[mt][nt][2] + bb.x, acc[mt][nt][3] + bb.y);
        }
    }
}

// ======================= tensorized windowed attention + LePE =======================
// one CTA = one (window, head). 128 threads = 4 warps. grid (4096, 6).
__global__ __launch_bounds__(128) void attn_kernel(
    const float* __restrict__ qkv, const float* __restrict__ pe_w,
    const float* __restrict__ pe_b, float* __restrict__ O)
{
    __shared__ float sQ[64 * 36];    // raw q
    __shared__ float sK[64 * 36];    // raw k
    __shared__ float sVt[32 * 68];   // v transposed [d][s], tf32-rounded
    __shared__ float sP[64 * 68];    // logits -> probs; first 64*36 used as raw-v staging
    __shared__ float sPE[32 * 12];
    __shared__ float sPEb[32];

    const uint32_t uQ = smem_u32(sQ), uK = smem_u32(sK), uVr = smem_u32(sP);

    const int w = blockIdx.x;
    const int h = blockIdx.y;
    const int bb = w >> 10;
    const int wy = (w & 1023) >> 5, wx = w & 31;
    const int tid = threadIdx.x;
    const int wid = tid >> 5, lane = tid & 31;
    const int g = lane >> 2, tg = lane & 3;

    // ---- gather q,k,v via cp.async (16B each) ----
#pragma unroll
    for (int i = 0; i < 12; i++) {
        int idx = tid + i * 128;        // 1536 float4
        int t = idx / 24, j = idx % 24;
        int which = j >> 3, c4 = j & 7;
        int n = (wy * 8 + (t >> 3)) * 256 + wx * 8 + (t & 7);
        const float* src = &qkv[((size_t)(bb * 65536 + n)) * 576 + h * 32 + which * 192 + c4 * 4];
        uint32_t dst = (which == 0 ? uQ : which == 1 ? uK : uVr) + (t * 36 + c4 * 4) * 4;
        cp_async16(dst, src);
    }
    CP_COMMIT();
    // pe weights
    for (int i = tid; i < 288; i += 128)
        sPE[(i / 9) * 12 + i % 9] = pe_w[h * 288 + i];
    if (tid < 32) sPEb[tid] = pe_b[h * 32 + tid];
    CP_WAIT0();
    __syncthreads();

    // ---- transpose v (raw in sP region) -> sVt[d][s], rounded ----
#pragma unroll
    for (int i = 0; i < 16; i++) {
        int idx = tid + i * 128;
        int s = idx >> 5, d = idx & 31;
        sVt[d * 68 + s] = rnd(sP[s * 36 + d]);
    }
    __syncthreads();

    // ---- logits(64x64) = q @ k^T, scaled; warp wid owns m-tile rows wid*16.. ----
    const int r0 = wid * 16 + g;
    {
        float bacc[8][4];
#pragma unroll
        for (int nt = 0; nt < 8; nt++)
#pragma unroll
            for (int j = 0; j < 4; j++) bacc[nt][j] = 0.f;
#pragma unroll
        for (int ks = 0; ks < 4; ks++) {
            const int k0 = ks * 8;
            uint32_t a[4];
            a[0] = to_tf32(sQ[r0 * 36 + k0 + tg]);
            a[1] = to_tf32(sQ[(r0 + 8) * 36 + k0 + tg]);
            a[2] = to_tf32(sQ[r0 * 36 + k0 + tg + 4]);
            a[3] = to_tf32(sQ[(r0 + 8) * 36 + k0 + tg + 4]);
#pragma unroll
            for (int nt = 0; nt < 8; nt++) {
                int n0 = nt * 8 + g;
                uint32_t b0 = to_tf32(sK[n0 * 36 + k0 + tg]);
                uint32_t b1 = to_tf32(sK[n0 * 36 + k0 + tg + 4]);
                mma_tf32(bacc[nt], a, b0, b1);
            }
        }
        const float scale = 0.17677669529663687f;
#pragma unroll
        for (int nt = 0; nt < 8; nt++) {
            int s = nt * 8 + tg * 2;
            sP[r0 * 68 + s]       = bacc[nt][0] * scale;
            sP[r0 * 68 + s + 1]   = bacc[nt][1] * scale;
            sP[(r0 + 8) * 68 + s]     = bacc[nt][2] * scale;
            sP[(r0 + 8) * 68 + s + 1] = bacc[nt][3] * scale;
        }
    }
    __syncthreads();

    // ---- softmax: 2 threads per row, 32 cols each; write rounded probs ----
    {
        int t = tid >> 1, q = tid & 1;
        float* row = sP + t * 68 + q * 32;
        float v[32];
#pragma unroll
        for (int j = 0; j < 8; j++) *(float4*)&v[j * 4] = *(float4*)&row[j * 4];
        float m = v[0];
#pragma unroll
        for (int j = 1; j < 32; j++) m = fmaxf(m, v[j]);
        m = fmaxf(m, __shfl_xor_sync(0xffffffffu, m, 1));
        float s = 0.f;
#pragma unroll
        for (int j = 0; j < 32; j++) { v[j] = __expf(v[j] - m); s += v[j]; }
        s += __shfl_xor_sync(0xffffffffu, s, 1);
        float inv = 1.0f / s;
#pragma unroll
        for (int j = 0; j < 32; j++) v[j] = rnd(v[j] * inv);
#pragma unroll
        for (int j = 0; j < 8; j++) *(float4*)&row[j * 4] = *(float4*)&v[j * 4];
    }
    __syncthreads();

    // ---- PV: o(64x32) = P @ v  (operands pre-rounded), + LePE, store ----
    {
        float dacc[4][4];
#pragma unroll
        for (int nt = 0; nt < 4; nt++)
#pragma unroll
            for (int j = 0; j < 4; j++) dacc[nt][j] = 0.f;
#pragma unroll
        for (int ks = 0; ks < 8; ks++) {
            const int k0 = ks * 8;
            uint32_t a[4];
            a[0] = __float_as_uint(sP[r0 * 68 + k0 + tg]);
            a[1] = __float_as_uint(sP[(r0 + 8) * 68 + k0 + tg]);
            a[2] = __float_as_uint(sP[r0 * 68 + k0 + tg + 4]);
            a[3] = __float_as_uint(sP[(r0 + 8) * 68 + k0 + tg + 4]);
#pragma unroll
            for (int nt = 0; nt < 4; nt++) {
                int n0 = nt * 8 + g;
                uint32_t b0 = __float_as_uint(sVt[n0 * 68 + k0 + tg]);
                uint32_t b1 = __float_as_uint(sVt[n0 * 68 + k0 + tg + 4]);
                mma_tf32(dacc[nt], a, b0, b1);
            }
        }
        // LePE + store
#pragma unroll
        for (int nt = 0; nt < 4; nt++) {
            const int d0 = nt * 8 + tg * 2;
            float pb0 = sPEb[d0], pb1 = sPEb[d0 + 1];
#pragma unroll
            for (int i = 0; i < 2; i++) {
                int t = r0 + i * 8;
                int ty = t >> 3, tx = t & 7;
                float l0 = pb0, l1 = pb1;
#pragma unroll
                for (int ky = 0; ky < 3; ky++) {
                    int yy = ty + ky - 1;
                    if (yy < 0 || yy > 7) continue;
#pragma unroll
                    for (int kx = 0; kx < 3; kx++) {
                        int xx = tx + kx - 1;
                        if (xx < 0 || xx > 7) continue;
                        int ss = yy * 8 + xx;
                        l0 += sPE[d0 * 12 + ky * 3 + kx] * sVt[d0 * 68 + ss];
                        l1 += sPE[(d0 + 1) * 12 + ky * 3 + kx] * sVt[(d0 + 1) * 68 + ss];
                    }
                }
                int n = (wy * 8 + ty) * 256 + wx * 8 + tx;
                size_t base = ((size_t)(bb * 65536 + n)) * 192 + h * 32 + d0;
                *(float2*)&O[base] = make_float2(dacc[nt][2 * i] + l0, dacc[nt][2 * i + 1] + l1);
            }
        }
    }
}

// ======================= launcher =======================
extern "C" void kernel_launch(void* const* d_in, const int* in_sizes, int n_in,
                              void* d_out, int out_size) {
    const float* x     = (const float*)d_in[0];
    const float* qkv_w = (const float*)d_in[1];
    const float* qkv_b = (const float*)d_in[2];
    const float* pe_w  = (const float*)d_in[3];
    const float* pe_b  = (const float*)d_in[4];
    const float* out_w = (const float*)d_in[5];
    const float* out_b = (const float*)d_in[6];
    float* out = (float*)d_out;

    const int B = in_sizes[0] / (65536 * 192);
    const int M = B * 65536;

    float *qkv_s, *o_s, *wq_s, *wo_s;
    cudaGetSymbolAddress((void**)&qkv_s, g_qkv);
    cudaGetSymbolAddress((void**)&o_s, g_o);
    cudaGetSymbolAddress((void**)&wq_s, g_wq);
    cudaGetSymbolAddress((void**)&wo_s, g_wo);

    static bool attr_set = false;
    if (!attr_set) {
        cudaFuncSetAttribute(gemm_tc, cudaFuncAttributeMaxDynamicSharedMemorySize, GEMM_SMEM);
        attr_set = true;
    }

    wconv_kernel<<<144, 256>>>(qkv_w, wq_s, 110592, out_w, wo_s, 36864);

    dim3 g1(6, M / 128);
    gemm_tc<<<g1, 256, GEMM_SMEM>>>(x, wq_s, qkv_b, qkv_s, M, 576, 192);

    dim3 g2(B * 1024, 6);
    attn_kernel<<<g2, 128>>>(qkv_s, pe_w, pe_b, o_s);

    dim3 g3(2, M / 128);
    gemm_tc<<<g3, 256, GEMM_SMEM>>>(o_s, wo_s, out_b, out, M, 192, 192);
}